// round 15
// baseline (speedup 1.0000x reference)
#include <cuda_runtime.h>
#include <cuda_fp16.h>
#include <math_constants.h>

#define D     128
#define NMET  20000
#define NRXN  50000
#define SLOTS 96        // bucket capacity per rxn (Poisson(20): P(>96) < 1e-25)
#define ROWS  8         // metabolite rows per precompute block

typedef unsigned long long ull;

// ---------------- scratch (static device globals; no allocation) -------------
__device__ float  g_exp[NMET];             // exp(gate) per metabolite (80KB, L1-resident)
__device__ __half g_Th[NMET * D];          // transformed rows in fp16 (5MB, L2-resident)
__device__ int    g_cnt[NRXN];             // per-rxn bucket fill
__device__ int    g_met[NRXN * SLOTS];     // bucketed metabolite ids per rxn
__device__ int    g_is64;
__device__ float4 g_Wtr[(D / 4) * D];      // Wt reordered: [k4][t] -> (w[4k4..4k4+3][t])
__device__ float4 g_W1r[(D / 4) * 64];     // W1 reordered: [k4][t] -> (w[4k4..4k4+3][t])

// ---------------- packed fp32x2 FMA (exact fp32 math, 2 MACs/slot) ------------
__device__ __forceinline__ void ffma2(ull& a, ull x, ull w) {
    asm("fma.rn.f32x2 %0, %1, %2, %0;" : "+l"(a) : "l"(x), "l"(w));
}
__device__ __forceinline__ float unpack_sum(ull v) {
    float lo, hi;
    asm("mov.b64 {%0, %1}, %2;" : "=f"(lo), "=f"(hi) : "l"(v));
    return lo + hi;
}

// ---------------- init: zero counts + detect index dtype ----------------------
__global__ void init_kernel(const int* __restrict__ w, int n_rxn) {
    int i = blockIdx.x * blockDim.x + threadIdx.x;
    if (i < n_rxn) g_cnt[i] = 0;
    if (blockIdx.x == 0 && threadIdx.x < 32) {
        // int64 little-endian with values < 2^31 -> odd 32-bit words all zero
        int t  = threadIdx.x;
        int nz = (w[2 * t + 1] != 0) | (w[2 * (t + 32) + 1] != 0);
        unsigned m = __ballot_sync(0xffffffffu, nz);
        if (t == 0) g_is64 = (m == 0) ? 1 : 0;
    }
}

// ---------------- reorder weights into pair-friendly layout -------------------
__global__ void reorder_kernel(const float* __restrict__ Wt,
                               const float* __restrict__ W1) {
    int i = blockIdx.x * blockDim.x + threadIdx.x;
    const int total_wt = (D / 4) * D;     // 4096
    const int total_w1 = (D / 4) * 64;    // 2048
    if (i < total_wt) {
        int k4 = i / D, t = i % D;
        g_Wtr[i] = make_float4(Wt[(4 * k4 + 0) * D + t], Wt[(4 * k4 + 1) * D + t],
                               Wt[(4 * k4 + 2) * D + t], Wt[(4 * k4 + 3) * D + t]);
    } else if (i < total_wt + total_w1) {
        int j = i - total_wt;
        int k4 = j / 64, t = j % 64;
        g_W1r[j] = make_float4(W1[(4 * k4 + 0) * 64 + t], W1[(4 * k4 + 1) * 64 + t],
                               W1[(4 * k4 + 2) * 64 + t], W1[(4 * k4 + 3) * 64 + t]);
    }
}

// ---------------- precompute: exp(gate) + fp16 transform ----------------------
// FFMA2 with zero in-loop packing: weights via LDG.128 pair-layout, features via
// LDS.128 ulonglong2. Exact fp32 math; 2 MACs per issue slot.
__global__ void precompute_kernel(const float* __restrict__ feats,
                                  const float* __restrict__ b1,
                                  const float* __restrict__ W2,
                                  const float* __restrict__ b2,
                                  const float* __restrict__ bt,
                                  int n_met) {
    __shared__ ulonglong2 f2[ROWS][D / 4];   // feature pairs, 128 floats per row
    __shared__ float      hred[ROWS][64];
    int t    = threadIdx.x;
    int warp = t >> 5;
    int lane = t & 31;

    int row0 = blockIdx.x * ROWS;
    if (row0 >= n_met) return;
    int nr = n_met - row0; if (nr > ROWS) nr = ROWS;

    #pragma unroll
    for (int r = 0; r < ROWS; ++r)
        ((float*)&f2[r][0])[t] = (r < nr) ? feats[(long long)(row0 + r) * D + t] : 0.f;
    __syncthreads();

    // transform: T[row][t] = relu(sum_k f[row][k] * Wt[k][t] + bt[t]) -> fp16
    {
        ull acc[ROWS];
        #pragma unroll
        for (int r = 0; r < ROWS; ++r) acc[r] = 0ull;
        const ulonglong2* Wp = (const ulonglong2*)g_Wtr;
        #pragma unroll 2
        for (int k4 = 0; k4 < D / 4; ++k4) {
            ulonglong2 w = Wp[k4 * D + t];       // (w[4k4],w[4k4+1]) , (w[4k4+2],w[4k4+3])
            #pragma unroll
            for (int r = 0; r < ROWS; ++r) {
                ulonglong2 x = f2[r][k4];        // (f[4k4],f[4k4+1]) , (f[4k4+2],f[4k4+3])
                ffma2(acc[r], x.x, w.x);
                ffma2(acc[r], x.y, w.y);
            }
        }
        float btv = bt[t];
        #pragma unroll
        for (int r = 0; r < ROWS; ++r)
            if (r < nr)
                g_Th[(long long)(row0 + r) * D + t] =
                    __float2half(fmaxf(unpack_sum(acc[r]) + btv, 0.f));
    }

    // gate hidden layer (threads t < 64)
    if (t < 64) {
        ull h[ROWS];
        #pragma unroll
        for (int r = 0; r < ROWS; ++r) h[r] = 0ull;
        const ulonglong2* W1p = (const ulonglong2*)g_W1r;
        #pragma unroll 2
        for (int k4 = 0; k4 < D / 4; ++k4) {
            ulonglong2 w = W1p[k4 * 64 + t];
            #pragma unroll
            for (int r = 0; r < ROWS; ++r) {
                ulonglong2 x = f2[r][k4];
                ffma2(h[r], x.x, w.x);
                ffma2(h[r], x.y, w.y);
            }
        }
        float b1v = b1[t], w2v = W2[t];
        #pragma unroll
        for (int r = 0; r < ROWS; ++r)
            hred[r][t] = fmaxf(unpack_sum(h[r]) + b1v, 0.f) * w2v;
    }
    __syncthreads();

    // warp w reduces rows w and w+4 -> gate scalar -> exp
    float b2v = b2[0];
    #pragma unroll
    for (int rr = 0; rr < 2; ++rr) {
        int r = warp + rr * 4;
        float v = hred[r][lane] + hred[r][lane + 32];
        #pragma unroll
        for (int o = 16; o; o >>= 1) v += __shfl_xor_sync(0xffffffffu, v, o);
        if (lane == 0 && r < nr) g_exp[row0 + r] = __expf(v + b2v);
    }
}

// ---------------- scatter: bucket met ids by rxn (R9-proven 2 edges/thread) ---
__device__ __forceinline__ void scatter_one(int met, int rxn) {
    int pos = atomicAdd(&g_cnt[rxn], 1);
    if (pos < SLOTS) g_met[rxn * SLOTS + pos] = met;
}

__global__ void scatter_kernel(const void* __restrict__ idx, long long E) {
    int is64 = g_is64;
    long long np = E >> 1;
    long long i = (long long)blockIdx.x * blockDim.x + threadIdx.x;
    long long stride = (long long)gridDim.x * blockDim.x;
    if (is64) {
        const longlong2* mv = (const longlong2*)idx;
        const longlong2* rv = (const longlong2*)((const long long*)idx + E);
        for (long long p = i; p < np; p += stride) {
            longlong2 m = mv[p];
            longlong2 r = rv[p];
            scatter_one((int)m.x, (int)r.x);
            scatter_one((int)m.y, (int)r.y);
        }
        if (i == 0 && (E & 1))
            scatter_one((int)((const long long*)idx)[E - 1],
                        (int)((const long long*)idx)[E + E - 1]);
    } else {
        const int2* mv = (const int2*)idx;
        const int2* rv = (const int2*)((const int*)idx + E);
        for (long long p = i; p < np; p += stride) {
            int2 m = mv[p];
            int2 r = rv[p];
            scatter_one(m.x, r.x);
            scatter_one(m.y, r.y);
        }
        if (i == 0 && (E & 1))
            scatter_one(((const int*)idx)[E - 1], ((const int*)idx)[E + E - 1]);
    }
}

// ---------------- per-reaction: two-pass softmax-weighted gather-sum ----------
// R9/R11/R13/R14-proven form (34.4us).
__device__ __forceinline__ void acc_row(float4& acc, float w, int met, int lane) {
    uint2 raw = *(const uint2*)(g_Th + (long long)met * D + lane * 4);
    __half2 h0 = *reinterpret_cast<const __half2*>(&raw.x);
    __half2 h1 = *reinterpret_cast<const __half2*>(&raw.y);
    float2 f0 = __half22float2(h0);
    float2 f1 = __half22float2(h1);
    acc.x = fmaf(w, f0.x, acc.x);
    acc.y = fmaf(w, f0.y, acc.y);
    acc.z = fmaf(w, f1.x, acc.z);
    acc.w = fmaf(w, f1.y, acc.w);
}

__global__ void rxn_kernel(float* __restrict__ Z, int n_rxn) {
    int gw   = (blockIdx.x * blockDim.x + threadIdx.x) >> 5;
    int lane = threadIdx.x & 31;
    if (gw >= n_rxn) return;

    int n = g_cnt[gw];
    if (n > SLOTS) n = SLOTS;
    const int* bucket = g_met + gw * SLOTS;

    float4 acc = make_float4(0.f, 0.f, 0.f, 0.f);

    if (n > 0) {
        // pass 1: sum of exp(gate) — coalesced met ids + L1-hit exp gathers
        float s = 0.f;
        for (int i = lane; i < n; i += 32) s += g_exp[bucket[i]];
        #pragma unroll
        for (int o = 16; o; o >>= 1) s += __shfl_xor_sync(0xffffffffu, s, o);
        float inv = 1.f / s;

        // pass 2: weighted accumulate, unrolled x4 for MLP
        int i = 0;
        for (; i + 4 <= n; i += 4) {
            int m0 = bucket[i], m1 = bucket[i + 1], m2 = bucket[i + 2], m3 = bucket[i + 3];
            float w0 = g_exp[m0] * inv;
            float w1 = g_exp[m1] * inv;
            float w2 = g_exp[m2] * inv;
            float w3 = g_exp[m3] * inv;
            acc_row(acc, w0, m0, lane);
            acc_row(acc, w1, m1, lane);
            acc_row(acc, w2, m2, lane);
            acc_row(acc, w3, m3, lane);
        }
        for (; i < n; ++i) {
            int m = bucket[i];
            acc_row(acc, g_exp[m] * inv, m, lane);
        }
    }

    *(float4*)(Z + (long long)gw * D + lane * 4) = acc;
}

// ---------------- launch: (reorder->precompute) overlaps (init->scatter) ------
extern "C" void kernel_launch(void* const* d_in, const int* in_sizes, int n_in,
                              void* d_out, int out_size) {
    const float* feats = (const float*)d_in[0];
    const void*  idx   = d_in[1];
    const float* W1    = (const float*)d_in[2];
    const float* b1    = (const float*)d_in[3];
    const float* W2    = (const float*)d_in[4];
    const float* b2    = (const float*)d_in[5];
    const float* Wt    = (const float*)d_in[6];
    const float* bt    = (const float*)d_in[7];
    float*       Z     = (float*)d_out;

    int       n_met = in_sizes[0] / D;
    long long E     = (long long)in_sizes[1] / 2;
    int       n_rxn = out_size / D;

    // one-time resources (created outside capture, on the first/correctness call)
    static cudaStream_t s_side = nullptr;
    static cudaEvent_t  ev_fork = nullptr, ev_join = nullptr;
    if (s_side == nullptr) {
        cudaStreamCreateWithFlags(&s_side, cudaStreamNonBlocking);
        cudaEventCreateWithFlags(&ev_fork, cudaEventDisableTiming);
        cudaEventCreateWithFlags(&ev_join, cudaEventDisableTiming);
    }

    // side stream: weight reorder -> precompute (FFMA2)
    cudaEventRecord(ev_fork, 0);
    cudaStreamWaitEvent(s_side, ev_fork, 0);
    reorder_kernel<<<(4096 + 2048 + 255) / 256, 256, 0, s_side>>>(Wt, W1);
    precompute_kernel<<<(n_met + ROWS - 1) / ROWS, 128, 0, s_side>>>(
        feats, b1, W2, b2, bt, n_met);
    cudaEventRecord(ev_join, s_side);

    // main stream: init -> bucket-scatter (independent of precompute)
    init_kernel<<<(n_rxn + 255) / 256, 256>>>((const int*)idx, n_rxn);
    scatter_kernel<<<2048, 256>>>(idx, E);

    // join: rxn needs g_exp/g_Th (side) + buckets (main)
    cudaStreamWaitEvent(0, ev_join, 0);
    rxn_kernel<<<(n_rxn + 7) / 8, 256>>>(Z, n_rxn);
}